// round 1
// baseline (speedup 1.0000x reference)
#include <cuda_runtime.h>
#include <cstdint>

#define T_TOK   4096
#define DMODEL  1024
#define DFF     4096
#define N_EXP   8
#define HCAP    9216   // sum of per-expert counts padded to 128: <= 8192 + 8*127

// ---------------- device scratch (static, no allocations) ----------------
__device__ int   g_cnt[N_EXP];
__device__ int   g_off[N_EXP + 1];
__device__ int   g_tok[N_EXP][T_TOK];
__device__ float g_gate[N_EXP][T_TOK];
__device__ float g_h[(size_t)HCAP * DFF];   // ~151 MB fp32 scratch for hidden acts

// ---------------- small helpers ----------------
__device__ __forceinline__ uint32_t f2tf(float f) {
    uint32_t r;
    asm("cvt.rna.tf32.f32 %0, %1;" : "=r"(r) : "f"(f));
    return r;
}

__device__ __forceinline__ float geluf(float x) {
    // tanh-approx GELU (jax.nn.gelu default): 0.5x(1+tanh(c(x+0.044715x^3)))
    // = x * sigmoid(2c(x+0.044715x^3)),  2c = 1.5957691216057308
    float u = x + 0.044715f * x * x * x;
    return x / (1.0f + __expf(-1.5957691216057308f * u));
}

__device__ __forceinline__ void cpa16(uint32_t s, const void* g) {
    asm volatile("cp.async.cg.shared.global [%0], [%1], 16;\n" :: "r"(s), "l"(g));
}

__device__ __forceinline__ void mma_tf32(float c[4], const uint32_t a[4], const uint32_t b[2]) {
    asm volatile(
        "mma.sync.aligned.m16n8k8.row.col.f32.tf32.tf32.f32 "
        "{%0,%1,%2,%3}, {%4,%5,%6,%7}, {%8,%9}, {%0,%1,%2,%3};\n"
        : "+f"(c[0]), "+f"(c[1]), "+f"(c[2]), "+f"(c[3])
        : "r"(a[0]), "r"(a[1]), "r"(a[2]), "r"(a[3]), "r"(b[0]), "r"(b[1]));
}

// ---------------- reset ----------------
__global__ void reset_kernel() {
    if (threadIdx.x < N_EXP) g_cnt[threadIdx.x] = 0;
}

// ---------------- router: logits -> softmax -> top2 -> expert lists ----------------
__global__ void router_kernel(const float* __restrict__ x, const float* __restrict__ Wg) {
    const int t   = blockIdx.x;
    const int tid = threadIdx.x;           // 128 threads
    float acc[8];
#pragma unroll
    for (int e = 0; e < 8; e++) acc[e] = 0.0f;

    const float* xr = x + (size_t)t * DMODEL;
    for (int d = tid; d < DMODEL; d += 128) {
        float xv = xr[d];
        const float4* w4 = reinterpret_cast<const float4*>(Wg + (size_t)d * 8);
        float4 w0 = w4[0], w1 = w4[1];
        acc[0] += xv * w0.x; acc[1] += xv * w0.y; acc[2] += xv * w0.z; acc[3] += xv * w0.w;
        acc[4] += xv * w1.x; acc[5] += xv * w1.y; acc[6] += xv * w1.z; acc[7] += xv * w1.w;
    }
#pragma unroll
    for (int e = 0; e < 8; e++)
#pragma unroll
        for (int o = 16; o > 0; o >>= 1)
            acc[e] += __shfl_down_sync(0xffffffffu, acc[e], o);

    __shared__ float sred[4][8];
    int wid = tid >> 5, lane = tid & 31;
    if (lane == 0) {
#pragma unroll
        for (int e = 0; e < 8; e++) sred[wid][e] = acc[e];
    }
    __syncthreads();
    if (tid == 0) {
        float l[8];
#pragma unroll
        for (int e = 0; e < 8; e++)
            l[e] = sred[0][e] + sred[1][e] + sred[2][e] + sred[3][e];
        // top-1 / top-2 with lowest-index tie break (matches jax.lax.top_k)
        int i1 = 0;
#pragma unroll
        for (int e = 1; e < 8; e++) if (l[e] > l[i1]) i1 = e;
        int i2 = (i1 == 0) ? 1 : 0;
#pragma unroll
        for (int e = 0; e < 8; e++) if (e != i1 && l[e] > l[i2]) i2 = e;

        float m = l[i1];
        float p[8], s = 0.0f;
#pragma unroll
        for (int e = 0; e < 8; e++) { p[e] = __expf(l[e] - m); s += p[e]; }
        float inv = 1.0f / s;

        int pos1 = atomicAdd(&g_cnt[i1], 1);
        g_tok[i1][pos1]  = t;
        g_gate[i1][pos1] = p[i1] * inv;
        int pos2 = atomicAdd(&g_cnt[i2], 1);
        g_tok[i2][pos2]  = t;
        g_gate[i2][pos2] = p[i2] * inv;
    }
}

// ---------------- offsets scan ----------------
__global__ void scan_kernel() {
    if (threadIdx.x == 0) {
        int o = 0;
#pragma unroll
        for (int e = 0; e < N_EXP; e++) {
            g_off[e] = o;
            o += (g_cnt[e] + 127) & ~127;
        }
        g_off[N_EXP] = o;
    }
}

// ---------------- grouped GEMM (tf32 mma.sync, 128x128x16 tiles, 3-stage cp.async) ----
// FIRST:  h = gelu( gather(x) @ W1[e] + b1[e] )   -> g_h
// !FIRST: out[tok] += gate * ( h @ W2[e] + b2[e] ) (atomicAdd scatter)
template <bool FIRST>
__global__ void __launch_bounds__(256)
moe_gemm_kernel(const float* __restrict__ X, const float* __restrict__ W,
                const float* __restrict__ bias, float* __restrict__ OUT) {
    constexpr int KTOT   = FIRST ? DMODEL : DFF;
    constexpr int NDIM   = FIRST ? DFF    : DMODEL;
    constexpr int KTILES = KTOT / 16;

    const int e     = blockIdx.z;
    const int cnt   = g_cnt[e];
    const int mtile = blockIdx.y;
    if (mtile * 128 >= cnt) return;
    const int ntile = blockIdx.x;
    const int roff  = g_off[e];

    __shared__ __align__(16) float sA[3][128 * 16];
    __shared__ __align__(16) float sB[3][16 * 128];

    const int tid  = threadIdx.x;
    const int lane = tid & 31, wid = tid >> 5;
    const int g    = lane >> 2, tig = lane & 3;
    const int warp_m = (wid & 1) * 64;
    const int warp_n = (wid >> 1) * 32;

    // ---- loader setup ----
    const int aq = tid & 3;
    const float* agp[2];
    uint32_t asoff[2];
#pragma unroll
    for (int i = 0; i < 2; i++) {
        int r = (tid >> 2) + 64 * i;
        const float* rp;
        if (FIRST) {
            int li  = mtile * 128 + r;
            int tok = (li < cnt) ? g_tok[e][li] : 0;  // padded rows gather token 0 (discarded)
            rp = X + (size_t)tok * DMODEL;
        } else {
            rp = g_h + (size_t)(roff + mtile * 128 + r) * DFF;
        }
        agp[i]   = rp + aq * 4;
        asoff[i] = (uint32_t)((r * 16 + ((aq ^ ((r >> 1) & 3)) << 2)) * 4);
    }
    const int bq = tid & 31;
    const float* bgp[2];
    uint32_t bsoff[2];
    const float* Wb = W + (size_t)e * KTOT * NDIM + (size_t)ntile * 128 + bq * 4;
#pragma unroll
    for (int i = 0; i < 2; i++) {
        int kr   = (tid >> 5) + 8 * i;
        bgp[i]   = Wb + (size_t)kr * NDIM;
        bsoff[i] = (uint32_t)((kr * 128 + ((bq ^ ((kr & 3) << 1)) << 2)) * 4);
    }
    uint32_t saB = (uint32_t)__cvta_generic_to_shared(&sA[0][0]);
    uint32_t sbB = (uint32_t)__cvta_generic_to_shared(&sB[0][0]);

    float acc[4][4][4];
#pragma unroll
    for (int a = 0; a < 4; a++)
#pragma unroll
        for (int b = 0; b < 4; b++)
#pragma unroll
            for (int c = 0; c < 4; c++) acc[a][b][c] = 0.0f;

    auto issue = [&](int kt) {
        int bufi = kt % 3;
        uint32_t sa = saB + bufi * (128 * 16 * 4);
        uint32_t sb = sbB + bufi * (16 * 128 * 4);
#pragma unroll
        for (int i = 0; i < 2; i++) cpa16(sa + asoff[i], agp[i] + (size_t)kt * 16);
#pragma unroll
        for (int i = 0; i < 2; i++) cpa16(sb + bsoff[i], bgp[i] + (size_t)kt * 16 * NDIM);
        asm volatile("cp.async.commit_group;\n");
    };

    issue(0);
    issue(1);

    for (int kt = 0; kt < KTILES; kt++) {
        if (kt + 1 < KTILES) asm volatile("cp.async.wait_group 1;\n");
        else                 asm volatile("cp.async.wait_group 0;\n");
        __syncthreads();
        if (kt + 2 < KTILES) issue(kt + 2);

        const float* A = sA[kt % 3];
        const float* B = sB[kt % 3];
#pragma unroll
        for (int ks = 0; ks < 2; ks++) {
            uint32_t af[4][4];
            const int kq = ks * 2;
#pragma unroll
            for (int mf = 0; mf < 4; mf++) {
                int m0 = warp_m + mf * 16 + g;
                int m1 = m0 + 8;
                int s0 = (m0 >> 1) & 3, s1 = (m1 >> 1) & 3;
                af[mf][0] = f2tf(A[m0 * 16 + ((kq ^ s0) << 2) + tig]);
                af[mf][1] = f2tf(A[m1 * 16 + ((kq ^ s1) << 2) + tig]);
                af[mf][2] = f2tf(A[m0 * 16 + (((kq + 1) ^ s0) << 2) + tig]);
                af[mf][3] = f2tf(A[m1 * 16 + (((kq + 1) ^ s1) << 2) + tig]);
            }
            uint32_t bf[4][2];
            const int k0 = ks * 8 + tig;
            const int k1 = k0 + 4;
            const int sw = tig << 1;   // (k&3)*2, identical for k0 and k1
#pragma unroll
            for (int nf = 0; nf < 4; nf++) {
                int c  = warp_n + nf * 8 + g;
                int cq = c >> 2, co = c & 3;
                bf[nf][0] = f2tf(B[k0 * 128 + ((cq ^ sw) << 2) + co]);
                bf[nf][1] = f2tf(B[k1 * 128 + ((cq ^ sw) << 2) + co]);
            }
#pragma unroll
            for (int mf = 0; mf < 4; mf++)
#pragma unroll
                for (int nf = 0; nf < 4; nf++)
                    mma_tf32(acc[mf][nf], af[mf], bf[nf]);
        }
    }

    // ---- epilogue ----
    const float* bp = bias + (size_t)e * NDIM + (size_t)ntile * 128;
    if (FIRST) {
        float* hb = g_h + (size_t)(roff + mtile * 128) * DFF + (size_t)ntile * 128;
#pragma unroll
        for (int mf = 0; mf < 4; mf++) {
            int r0 = warp_m + mf * 16 + g;
#pragma unroll
            for (int nf = 0; nf < 4; nf++) {
                int c = warp_n + nf * 8 + tig * 2;
                float b0 = bp[c], b1 = bp[c + 1];
                float2 v0 = make_float2(geluf(acc[mf][nf][0] + b0),
                                        geluf(acc[mf][nf][1] + b1));
                float2 v1 = make_float2(geluf(acc[mf][nf][2] + b0),
                                        geluf(acc[mf][nf][3] + b1));
                *reinterpret_cast<float2*>(hb + (size_t)r0 * DFF + c)       = v0;
                *reinterpret_cast<float2*>(hb + (size_t)(r0 + 8) * DFF + c) = v1;
            }
        }
    } else {
#pragma unroll
        for (int mf = 0; mf < 4; mf++) {
#pragma unroll
            for (int half = 0; half < 2; half++) {
                int li = mtile * 128 + warp_m + mf * 16 + g + half * 8;
                if (li < cnt) {
                    int   t = g_tok[e][li];
                    float w = g_gate[e][li];
                    float* ob = OUT + (size_t)t * DMODEL + (size_t)ntile * 128;
#pragma unroll
                    for (int nf = 0; nf < 4; nf++) {
                        int c = warp_n + nf * 8 + tig * 2;
                        float v0 = (acc[mf][nf][half * 2 + 0] + bp[c])     * w;
                        float v1 = (acc[mf][nf][half * 2 + 1] + bp[c + 1]) * w;
                        atomicAdd(ob + c,     v0);
                        atomicAdd(ob + c + 1, v1);
                    }
                }
            }
        }
    }
}

// ---------------- launch ----------------
extern "C" void kernel_launch(void* const* d_in, const int* in_sizes, int n_in,
                              void* d_out, int out_size) {
    const float* x  = (const float*)d_in[0];
    const float* Wg = (const float*)d_in[1];
    const float* W1 = (const float*)d_in[2];
    const float* b1 = (const float*)d_in[3];
    const float* W2 = (const float*)d_in[4];
    const float* b2 = (const float*)d_in[5];
    float* out = (float*)d_out;

    reset_kernel<<<1, 32>>>();
    cudaMemsetAsync(d_out, 0, (size_t)out_size * sizeof(float));
    router_kernel<<<T_TOK, 128>>>(x, Wg);
    scan_kernel<<<1, 1>>>();
    moe_gemm_kernel<true ><<<dim3(DFF / 128,    32, N_EXP), 256>>>(x,       W1, b1, nullptr);
    moe_gemm_kernel<false><<<dim3(DMODEL / 128, 32, N_EXP), 256>>>(nullptr, W2, b2, out);
}

// round 5
// speedup vs baseline: 1.6641x; 1.6641x over previous
#include <cuda_runtime.h>
#include <cuda_fp16.h>
#include <cstdint>

#define T_TOK   4096
#define DMODEL  1024
#define DFF     4096
#define N_EXP   8
#define HCAP    9216
#define STAGE_BYTES 32768   // A 16KB + B 16KB (fp16 128x64 each)

// ---------------- device scratch (static) ----------------
__device__ int    g_cnt[N_EXP];
__device__ int    g_off[N_EXP + 1];
__device__ int    g_tok[N_EXP][T_TOK];
__device__ float  g_gate[N_EXP][T_TOK];
__device__ int    g_slot[N_EXP][T_TOK];
__device__ __half g_x16[(size_t)T_TOK * DMODEL];
__device__ __half g_h16[(size_t)HCAP * DFF];
__device__ __half g_w1t[(size_t)N_EXP * DFF * DMODEL];   // [e][h][d] K-major for GEMM1 B
__device__ __half g_w2t[(size_t)N_EXP * DMODEL * DFF];   // [e][d][h] K-major for GEMM2 B
__device__ float  g_y[2][(size_t)T_TOK * DMODEL];

// ---------------- helpers ----------------
__device__ __forceinline__ uint32_t smem_u32(const void* p) {
    uint32_t a;
    asm("{ .reg .u64 t; cvta.to.shared.u64 t, %1; cvt.u32.u64 %0, t; }" : "=r"(a) : "l"(p));
    return a;
}
__device__ __forceinline__ float geluf(float x) {
    float u = x + 0.044715f * x * x * x;
    return x / (1.0f + __expf(-1.5957691216057308f * u));
}
__device__ __forceinline__ void cpa16(uint32_t s, const void* g) {
    asm volatile("cp.async.cg.shared.global [%0], [%1], 16;\n" :: "r"(s), "l"(g));
}
__device__ __forceinline__ void ldmx4(uint32_t r[4], uint32_t addr) {
    asm volatile("ldmatrix.sync.aligned.m8n8.x4.shared.b16 {%0,%1,%2,%3}, [%4];"
                 : "=r"(r[0]), "=r"(r[1]), "=r"(r[2]), "=r"(r[3]) : "r"(addr));
}
__device__ __forceinline__ void ldmx2(uint32_t r[2], uint32_t addr) {
    asm volatile("ldmatrix.sync.aligned.m8n8.x2.shared.b16 {%0,%1}, [%2];"
                 : "=r"(r[0]), "=r"(r[1]) : "r"(addr));
}
__device__ __forceinline__ void mma_f16(float c[4], const uint32_t a[4], const uint32_t b[2]) {
    asm volatile(
        "mma.sync.aligned.m16n8k16.row.col.f32.f16.f16.f32 "
        "{%0,%1,%2,%3}, {%4,%5,%6,%7}, {%8,%9}, {%0,%1,%2,%3};\n"
        : "+f"(c[0]), "+f"(c[1]), "+f"(c[2]), "+f"(c[3])
        : "r"(a[0]), "r"(a[1]), "r"(a[2]), "r"(a[3]), "r"(b[0]), "r"(b[1]));
}

// ---------------- small kernels ----------------
__global__ void reset_kernel() { if (threadIdx.x < N_EXP) g_cnt[threadIdx.x] = 0; }

__global__ void router_kernel(const float* __restrict__ x, const float* __restrict__ Wg) {
    const int t = blockIdx.x, tid = threadIdx.x;
    float acc[8];
#pragma unroll
    for (int e = 0; e < 8; e++) acc[e] = 0.0f;
    const float* xr = x + (size_t)t * DMODEL;
    for (int d = tid; d < DMODEL; d += 128) {
        float xv = xr[d];
        const float4* w4 = reinterpret_cast<const float4*>(Wg + (size_t)d * 8);
        float4 w0 = w4[0], w1 = w4[1];
        acc[0] += xv * w0.x; acc[1] += xv * w0.y; acc[2] += xv * w0.z; acc[3] += xv * w0.w;
        acc[4] += xv * w1.x; acc[5] += xv * w1.y; acc[6] += xv * w1.z; acc[7] += xv * w1.w;
    }
#pragma unroll
    for (int e = 0; e < 8; e++)
#pragma unroll
        for (int o = 16; o > 0; o >>= 1) acc[e] += __shfl_down_sync(0xffffffffu, acc[e], o);
    __shared__ float sred[4][8];
    int wid = tid >> 5, lane = tid & 31;
    if (lane == 0)
#pragma unroll
        for (int e = 0; e < 8; e++) sred[wid][e] = acc[e];
    __syncthreads();
    if (tid == 0) {
        float l[8];
#pragma unroll
        for (int e = 0; e < 8; e++) l[e] = sred[0][e] + sred[1][e] + sred[2][e] + sred[3][e];
        int i1 = 0;
#pragma unroll
        for (int e = 1; e < 8; e++) if (l[e] > l[i1]) i1 = e;
        int i2 = (i1 == 0) ? 1 : 0;
#pragma unroll
        for (int e = 0; e < 8; e++) if (e != i1 && l[e] > l[i2]) i2 = e;
        float m = l[i1], p[8], s = 0.0f;
#pragma unroll
        for (int e = 0; e < 8; e++) { p[e] = __expf(l[e] - m); s += p[e]; }
        float inv = 1.0f / s;
        int pos1 = atomicAdd(&g_cnt[i1], 1);
        g_tok[i1][pos1] = t; g_gate[i1][pos1] = p[i1] * inv; g_slot[i1][pos1] = 0;
        int pos2 = atomicAdd(&g_cnt[i2], 1);
        g_tok[i2][pos2] = t; g_gate[i2][pos2] = p[i2] * inv; g_slot[i2][pos2] = 1;
    }
}

__global__ void scan_kernel() {
    if (threadIdx.x == 0) {
        int o = 0;
#pragma unroll
        for (int e = 0; e < N_EXP; e++) { g_off[e] = o; o += (g_cnt[e] + 127) & ~127; }
        g_off[N_EXP] = o;
    }
}

__global__ void convert_x_kernel(const float* __restrict__ x) {
    size_t i = ((size_t)blockIdx.x * 256 + threadIdx.x) * 4;
    float4 v = *reinterpret_cast<const float4*>(x + i);
    *reinterpret_cast<half2*>(&g_x16[i])     = __floats2half2_rn(v.x, v.y);
    *reinterpret_cast<half2*>(&g_x16[i + 2]) = __floats2half2_rn(v.z, v.w);
}

// in: [e][R][C] fp32  ->  out: [e][C][R] fp16   (out selected by `which`)
__global__ void transpose_convert_kernel(const float* __restrict__ in, int R, int C, int which) {
    __shared__ float tile[32][33];
    const int e = blockIdx.z;
    const float* ip = in + (size_t)e * R * C;
    __half* op = (which ? g_w2t : g_w1t) + (size_t)e * R * C;
    const int c0 = blockIdx.x * 32, r0 = blockIdx.y * 32;
    const int tx = threadIdx.x, ty = threadIdx.y;   // 32 x 8
#pragma unroll
    for (int i = 0; i < 4; i++)
        tile[ty + i * 8][tx] = ip[(size_t)(r0 + ty + i * 8) * C + c0 + tx];
    __syncthreads();
#pragma unroll
    for (int i = 0; i < 4; i++)
        op[(size_t)(c0 + ty + i * 8) * R + r0 + tx] = __float2half_rn(tile[tx][ty + i * 8]);
}

__global__ void combine_kernel(float* __restrict__ out) {
    size_t i = ((size_t)blockIdx.x * 256 + threadIdx.x) * 4;
    float4 a = *reinterpret_cast<const float4*>(&g_y[0][i]);
    float4 b = *reinterpret_cast<const float4*>(&g_y[1][i]);
    *reinterpret_cast<float4*>(out + i) =
        make_float4(a.x + b.x, a.y + b.y, a.z + b.z, a.w + b.w);
}

// ---------------- fp16 grouped GEMM: 128x128x64 tiles, 3-stage cp.async ----------------
// FIRST:  h16 = gelu( gather(x16) @ W1t^T + b1 )     (B = g_w1t [e][n=h][k=d])
// !FIRST: g_y[slot][tok] = gate * ( h16 @ W2t^T + b2 ) (B = g_w2t [e][n=d][k=h])
template <bool FIRST>
__global__ void __launch_bounds__(256, 2)
moe_gemm_fp16(const float* __restrict__ bias) {
    constexpr int KTOT = FIRST ? DMODEL : DFF;
    constexpr int NDIM = FIRST ? DFF : DMODEL;
    constexpr int KT   = KTOT / 64;

    const int e = blockIdx.z;
    const int cnt = g_cnt[e];
    const int mtile = blockIdx.y;
    if (mtile * 128 >= cnt) return;
    const int ntile = blockIdx.x;
    const int roff = g_off[e];

    extern __shared__ __align__(1024) char smraw[];
    const uint32_t smem_u = smem_u32(smraw);

    const int tid = threadIdx.x;
    const int lane = tid & 31, wid = tid >> 5;
    const int warp_m = (wid & 1) * 64;
    const int warp_n = (wid >> 1) * 32;

    // ---- cp.async source/dest setup: thread -> (row, half of 64-col row) ----
    const int arow = tid >> 1, ahalf = tid & 1;
    const __half* aptr;
    if (FIRST) {
        int li = mtile * 128 + arow;
        int tok = (li < cnt) ? g_tok[e][li] : g_tok[e][0];
        aptr = g_x16 + (size_t)tok * DMODEL + ahalf * 32;
    } else {
        aptr = g_h16 + (size_t)(roff + mtile * 128 + arow) * DFF + ahalf * 32;
    }
    const __half* bptr = (FIRST ? g_w1t : g_w2t)
        + ((size_t)e * NDIM + ntile * 128 + arow) * KTOT + ahalf * 32;

    uint32_t drel[4];
#pragma unroll
    for (int j = 0; j < 4; j++) {
        int ch = ahalf * 4 + j;
        drel[j] = (uint32_t)(arow * 128 + ((ch ^ (arow & 7)) << 4));
    }

    auto issue = [&](int kt, int buf) {
        uint32_t base = smem_u + buf * STAGE_BYTES;
        const __half* as = aptr + kt * 64;
        const __half* bs = bptr + kt * 64;
#pragma unroll
        for (int j = 0; j < 4; j++) cpa16(base + drel[j], as + j * 8);
#pragma unroll
        for (int j = 0; j < 4; j++) cpa16(base + 16384 + drel[j], bs + j * 8);
        asm volatile("cp.async.commit_group;\n");
    };

    // ---- fragment address precompute (relative to stage base) ----
    const int swz = lane & 7;
    uint32_t arow128[4], brow128[4];
#pragma unroll
    for (int mf = 0; mf < 4; mf++)
        arow128[mf] = (uint32_t)((warp_m + mf * 16 + (lane & 15)) * 128);
#pragma unroll
    for (int nf = 0; nf < 4; nf++)
        brow128[nf] = (uint32_t)(16384 + (warp_n + nf * 8 + (lane & 7)) * 128);
    const int achsel = lane >> 4;          // 0/1
    const int bchsel = (lane >> 3) & 1;    // 0/1

    float acc[4][4][4];
#pragma unroll
    for (int a = 0; a < 4; a++)
#pragma unroll
        for (int b = 0; b < 4; b++)
#pragma unroll
            for (int c = 0; c < 4; c++) acc[a][b][c] = 0.0f;

    issue(0, 0);
    issue(1, 1);

    int buf = 0, ibuf = 2;
    for (int kt = 0; kt < KT; kt++) {
        if (kt + 1 < KT) asm volatile("cp.async.wait_group 1;\n");
        else             asm volatile("cp.async.wait_group 0;\n");
        __syncthreads();
        if (kt + 2 < KT) {
            issue(kt + 2, ibuf);
            if (++ibuf == 3) ibuf = 0;
        }
        const uint32_t base = smem_u + buf * STAGE_BYTES;
        if (++buf == 3) buf = 0;

#pragma unroll
        for (int ks = 0; ks < 4; ks++) {
            uint32_t a[4][4], b[4][2];
            const int cha = 2 * ks + achsel;
            const int chb = 2 * ks + bchsel;
#pragma unroll
            for (int mf = 0; mf < 4; mf++)
                ldmx4(a[mf], base + arow128[mf] + (((uint32_t)(cha ^ swz)) << 4));
#pragma unroll
            for (int nf = 0; nf < 4; nf++)
                ldmx2(b[nf], base + brow128[nf] + (((uint32_t)(chb ^ swz)) << 4));
#pragma unroll
            for (int mf = 0; mf < 4; mf++)
#pragma unroll
                for (int nf = 0; nf < 4; nf++)
                    mma_f16(acc[mf][nf], a[mf], b[nf]);
        }
    }

    // ---- epilogue ----
    const float* bp = bias + (size_t)e * NDIM + (size_t)ntile * 128;
    const int mlo = lane >> 2;          // 0..7
    const int ncol = (lane & 3) * 2;

    if (FIRST) {
#pragma unroll
        for (int mf = 0; mf < 4; mf++) {
#pragma unroll
            for (int half = 0; half < 2; half++) {
                int row = roff + mtile * 128 + warp_m + mf * 16 + mlo + half * 8;
                __half* hr = g_h16 + (size_t)row * DFF + (size_t)ntile * 128;
#pragma unroll
                for (int nf = 0; nf < 4; nf++) {
                    int c = warp_n + nf * 8 + ncol;
                    float v0 = geluf(acc[mf][nf][half * 2 + 0] + bp[c]);
                    float v1 = geluf(acc[mf][nf][half * 2 + 1] + bp[c + 1]);
                    *reinterpret_cast<half2*>(hr + c) = __floats2half2_rn(v0, v1);
                }
            }
        }
    } else {
#pragma unroll
        for (int mf = 0; mf < 4; mf++) {
#pragma unroll
            for (int half = 0; half < 2; half++) {
                int li = mtile * 128 + warp_m + mf * 16 + mlo + half * 8;
                if (li < cnt) {
                    int   t = g_tok[e][li];
                    float w = g_gate[e][li];
                    int   sl = g_slot[e][li];
                    float* orow = &g_y[sl][(size_t)t * DMODEL + (size_t)ntile * 128];
#pragma unroll
                    for (int nf = 0; nf < 4; nf++) {
                        int c = warp_n + nf * 8 + ncol;
                        float2 v;
                        v.x = (acc[mf][nf][half * 2 + 0] + bp[c])     * w;
                        v.y = (acc[mf][nf][half * 2 + 1] + bp[c + 1]) * w;
                        *reinterpret_cast<float2*>(orow + c) = v;
                    }
                }
            }
        }
    }
}

// ---------------- launch ----------------
extern "C" void kernel_launch(void* const* d_in, const int* in_sizes, int n_in,
                              void* d_out, int out_size) {
    const float* x  = (const float*)d_in[0];
    const float* Wg = (const float*)d_in[1];
    const float* W1 = (const float*)d_in[2];
    const float* b1 = (const float*)d_in[3];
    const float* W2 = (const float*)d_in[4];
    const float* b2 = (const float*)d_in[5];
    float* out = (float*)d_out;

    const int smem_bytes = 3 * STAGE_BYTES;
    cudaFuncSetAttribute(moe_gemm_fp16<true>,  cudaFuncAttributeMaxDynamicSharedMemorySize, smem_bytes);
    cudaFuncSetAttribute(moe_gemm_fp16<false>, cudaFuncAttributeMaxDynamicSharedMemorySize, smem_bytes);

    reset_kernel<<<1, 32>>>();
    router_kernel<<<T_TOK, 128>>>(x, Wg);
    scan_kernel<<<1, 1>>>();
    convert_x_kernel<<<(T_TOK * DMODEL) / 1024, 256>>>(x);
    transpose_convert_kernel<<<dim3(DFF / 32,    DMODEL / 32, N_EXP), dim3(32, 8)>>>(W1, DMODEL, DFF, 0);
    transpose_convert_kernel<<<dim3(DMODEL / 32, DFF / 32,    N_EXP), dim3(32, 8)>>>(W2, DFF, DMODEL, 1);

    moe_gemm_fp16<true ><<<dim3(DFF / 128,    32, N_EXP), 256, smem_bytes>>>(b1);
    moe_gemm_fp16<false><<<dim3(DMODEL / 128, 32, N_EXP), 256, smem_bytes>>>(b2);
    combine_kernel<<<(T_TOK * DMODEL) / 1024, 256>>>(out);
}